// round 1
// baseline (speedup 1.0000x reference)
#include <cuda_runtime.h>
#include <math.h>

#define NN 100000

// Scratch (device globals — no allocations allowed)
__device__ __align__(256) float g_sup[NN * 64];  // support (max width 64)
__device__ __align__(256) float g_agg[NN * 64];  // aggregation target
__device__ __align__(256) float g_h[NN * 64];    // hidden state

// ---------------------------------------------------------------------------
// Vector no-return atomic add (RED.E.ADD.F32 x4), sm_90+
// ---------------------------------------------------------------------------
__device__ __forceinline__ void red_add_v4(float* addr, float4 v) {
    asm volatile("red.global.add.v4.f32 [%0], {%1,%2,%3,%4};"
                 :: "l"(addr), "f"(v.x), "f"(v.y), "f"(v.z), "f"(v.w)
                 : "memory");
}

// ---------------------------------------------------------------------------
// Tiled fp32 GEMM: C[M,OUTC] = A[M,K] @ W[K,OUTC]   (K in {64,128}, OUTC<=64)
// 64-row x 64-col tile, 256 threads, 4x4 register blocking per thread.
// ---------------------------------------------------------------------------
template <int K, int OUTC>
__global__ __launch_bounds__(256) void gemm_kernel(
    const float* __restrict__ A, const float* __restrict__ W,
    float* __restrict__ C, int M)
{
    __shared__ float a_s[64][33];   // [row][k], padded (conflict-free col reads)
    __shared__ float b_s[32][64];   // [k][col]

    const int tid = threadIdx.x;
    const int tx = tid & 15;        // col group (4 cols each)
    const int ty = tid >> 4;        // row group (4 rows each)
    const int row0 = blockIdx.x * 64;

    float acc[4][4] = {};

    for (int k0 = 0; k0 < K; k0 += 32) {
        // Load A tile: 64 rows x 32 k, coalesced over k
        {
            const int k = tid & 31;
            const int r = tid >> 5;  // 0..7
            #pragma unroll
            for (int i = 0; i < 8; i++) {
                const int row = r + i * 8;
                const int grow = row0 + row;
                float v = 0.f;
                if (grow < M) v = A[(size_t)grow * K + k0 + k];
                a_s[row][k] = v;
            }
        }
        // Load B tile: 32 k x 64 cols (zero-pad beyond OUTC), coalesced over c
        {
            const int c = tid & 63;
            const int kb = tid >> 6;  // 0..3
            #pragma unroll
            for (int i = 0; i < 8; i++) {
                const int kk = kb + i * 4;
                float v = 0.f;
                if (OUTC == 64 || c < OUTC) v = W[(k0 + kk) * OUTC + c];
                b_s[kk][c] = v;
            }
        }
        __syncthreads();

        #pragma unroll
        for (int kk = 0; kk < 32; kk++) {
            const float a0 = a_s[ty * 4 + 0][kk];
            const float a1 = a_s[ty * 4 + 1][kk];
            const float a2 = a_s[ty * 4 + 2][kk];
            const float a3 = a_s[ty * 4 + 3][kk];
            const float4 b = *(const float4*)&b_s[kk][tx * 4];
            acc[0][0] += a0 * b.x; acc[0][1] += a0 * b.y; acc[0][2] += a0 * b.z; acc[0][3] += a0 * b.w;
            acc[1][0] += a1 * b.x; acc[1][1] += a1 * b.y; acc[1][2] += a1 * b.z; acc[1][3] += a1 * b.w;
            acc[2][0] += a2 * b.x; acc[2][1] += a2 * b.y; acc[2][2] += a2 * b.z; acc[2][3] += a2 * b.w;
            acc[3][0] += a3 * b.x; acc[3][1] += a3 * b.y; acc[3][2] += a3 * b.z; acc[3][3] += a3 * b.w;
        }
        __syncthreads();
    }

    const int c = tx * 4;
    if (OUTC == 64 || c < OUTC) {
        #pragma unroll
        for (int i = 0; i < 4; i++) {
            const int row = row0 + ty * 4 + i;
            if (row < M) {
                *(float4*)&C[(size_t)row * OUTC + c] =
                    make_float4(acc[i][0], acc[i][1], acc[i][2], acc[i][3]);
            }
        }
    }
}

// ---------------------------------------------------------------------------
// Edge scatter: for each edge e: agg[tgt[e]] += sup[src[e]] * w[e]
// 16 lanes per edge, one float4 per lane (COLS=64 -> 16 f4; COLS=40 -> 10 f4)
// ---------------------------------------------------------------------------
template <int COLS>
__global__ __launch_bounds__(256) void scatter_kernel(
    const float* __restrict__ sup,
    const int* __restrict__ src, const int* __restrict__ tgt,
    const float* __restrict__ w,
    float* __restrict__ agg, int E)
{
    constexpr int F4 = COLS / 4;
    const int gid = blockIdx.x * blockDim.x + threadIdx.x;
    const int lane = gid & 15;
    const int e = gid >> 4;
    if (e >= E) return;
    const int s = src[e];
    const int t = tgt[e];
    const float ww = w[e];
    if (lane < F4) {
        float4 v = ((const float4*)(sup + (size_t)s * COLS))[lane];
        v.x *= ww; v.y *= ww; v.z *= ww; v.w *= ww;
        red_add_v4((float*)(((float4*)(agg + (size_t)t * COLS)) + lane), v);
    }
}

// ---------------------------------------------------------------------------
// Epilogue (width 64): h = relu(agg + bias) [+ h  if residual]
// ---------------------------------------------------------------------------
template <bool RESIDUAL>
__global__ __launch_bounds__(256) void epilogue_kernel(
    float* __restrict__ h, const float* __restrict__ agg,
    const float* __restrict__ bias, int n4)
{
    const int i = blockIdx.x * blockDim.x + threadIdx.x;
    if (i >= n4) return;
    const int c4 = i & 15;
    const float4 b = ((const float4*)bias)[c4];
    float4 v = ((const float4*)agg)[i];
    v.x = fmaxf(v.x + b.x, 0.f);
    v.y = fmaxf(v.y + b.y, 0.f);
    v.z = fmaxf(v.z + b.z, 0.f);
    v.w = fmaxf(v.w + b.w, 0.f);
    if (RESIDUAL) {
        const float4 r = ((const float4*)h)[i];
        v.x += r.x; v.y += r.y; v.z += r.z; v.w += r.w;
    }
    ((float4*)h)[i] = v;
}

// ---------------------------------------------------------------------------
// Final: out = log_softmax(agg + b3) over 40 cols. One warp per row.
// ---------------------------------------------------------------------------
__global__ __launch_bounds__(256) void final_kernel(
    const float* __restrict__ agg, const float* __restrict__ b3,
    float* __restrict__ out, int M)
{
    const int warp = (blockIdx.x * blockDim.x + threadIdx.x) >> 5;
    const int lane = threadIdx.x & 31;
    if (warp >= M) return;
    const float* r = agg + (size_t)warp * 40;
    float v0 = r[lane] + b3[lane];
    float v1 = (lane < 8) ? (r[32 + lane] + b3[32 + lane]) : -INFINITY;

    float m = fmaxf(v0, v1);
    #pragma unroll
    for (int o = 16; o > 0; o >>= 1)
        m = fmaxf(m, __shfl_xor_sync(0xFFFFFFFFu, m, o));

    float s = expf(v0 - m) + ((lane < 8) ? expf(v1 - m) : 0.f);
    #pragma unroll
    for (int o = 16; o > 0; o >>= 1)
        s += __shfl_xor_sync(0xFFFFFFFFu, s, o);

    const float lse = m + logf(s);
    float* o = out + (size_t)warp * 40;
    o[lane] = v0 - lse;
    if (lane < 8) o[32 + lane] = v1 - lse;
}

// ---------------------------------------------------------------------------
// Launch
// ---------------------------------------------------------------------------
extern "C" void kernel_launch(void* const* d_in, const int* in_sizes, int n_in,
                              void* d_out, int out_size)
{
    const float* x     = (const float*)d_in[0];   // [N,128]
    const int*   src   = (const int*)d_in[1];     // [E]
    const int*   tgt   = (const int*)d_in[2];     // [E]
    const float* mw    = (const float*)d_in[3];   // [E]
    const float* W0    = (const float*)d_in[4];
    const float* b0    = (const float*)d_in[5];
    const float* W1    = (const float*)d_in[6];
    const float* b1    = (const float*)d_in[7];
    const float* W2    = (const float*)d_in[8];
    const float* b2    = (const float*)d_in[9];
    const float* W3    = (const float*)d_in[10];
    const float* b3    = (const float*)d_in[11];
    float* out = (float*)d_out;

    const int M = NN;
    const int E = in_sizes[1];

    float *sup, *agg, *h;
    cudaGetSymbolAddress((void**)&sup, g_sup);
    cudaGetSymbolAddress((void**)&agg, g_agg);
    cudaGetSymbolAddress((void**)&h,   g_h);

    const int gemm_blocks = (M + 63) / 64;
    const int scat_blocks64 = (E * 16 + 255) / 256;
    const int epi_n4 = M * 16;
    const int epi_blocks = (epi_n4 + 255) / 256;

    // ---- Layer 0: h = relu(agg(x@W0) + b0)
    gemm_kernel<128, 64><<<gemm_blocks, 256>>>(x, W0, sup, M);
    cudaMemsetAsync(agg, 0, (size_t)M * 64 * sizeof(float));
    scatter_kernel<64><<<scat_blocks64, 256>>>(sup, src, tgt, mw, agg, E);
    epilogue_kernel<false><<<epi_blocks, 256>>>(h, agg, b0, epi_n4);

    // ---- Layer 1: h = relu(agg(h@W1) + b1) + h
    gemm_kernel<64, 64><<<gemm_blocks, 256>>>(h, W1, sup, M);
    cudaMemsetAsync(agg, 0, (size_t)M * 64 * sizeof(float));
    scatter_kernel<64><<<scat_blocks64, 256>>>(sup, src, tgt, mw, agg, E);
    epilogue_kernel<true><<<epi_blocks, 256>>>(h, agg, b1, epi_n4);

    // ---- Layer 2: h = relu(agg(h@W2) + b2) + h
    gemm_kernel<64, 64><<<gemm_blocks, 256>>>(h, W2, sup, M);
    cudaMemsetAsync(agg, 0, (size_t)M * 64 * sizeof(float));
    scatter_kernel<64><<<scat_blocks64, 256>>>(sup, src, tgt, mw, agg, E);
    epilogue_kernel<true><<<epi_blocks, 256>>>(h, agg, b2, epi_n4);

    // ---- Layer 3: out = log_softmax(agg(h@W3) + b3)
    gemm_kernel<64, 40><<<gemm_blocks, 256>>>(h, W3, sup, M);
    cudaMemsetAsync(agg, 0, (size_t)M * 40 * sizeof(float));
    scatter_kernel<40><<<scat_blocks64, 256>>>(sup, src, tgt, mw, agg, E);
    final_kernel<<<(M * 32 + 255) / 256, 256>>>(agg, b3, out, M);
}

// round 2
// speedup vs baseline: 1.6432x; 1.6432x over previous
#include <cuda_runtime.h>
#include <math.h>

#define NN 100000
#define EE 1600000

// Scratch (device globals — no allocations allowed)
__device__ __align__(256) float g_sup[NN * 64];      // GEMM output (support)
__device__ __align__(256) float g_h[NN * 64];        // hidden state
__device__ __align__(256) int   g_cnt[NN + 1];       // counts -> row offsets
__device__ __align__(256) int   g_cur[NN];           // fill cursors
__device__ __align__(256) int2  g_edge[EE];          // CSR payload: (src, w bits)
__device__ __align__(256) int   g_blksum[256];       // scan partials

// ---------------------------------------------------------------------------
// CSR build: histogram -> scan (3 pass) -> fill
// ---------------------------------------------------------------------------
__global__ __launch_bounds__(256) void hist_kernel(
    const int* __restrict__ tgt, int* __restrict__ cnt, int E)
{
    int e = blockIdx.x * 256 + threadIdx.x;
    if (e < E) atomicAdd(&cnt[tgt[e] + 1], 1);
}

__global__ __launch_bounds__(1024) void scan1_kernel(
    int* __restrict__ data, int n, int* __restrict__ blksum)
{
    __shared__ int sh[1024];
    const int tid = threadIdx.x;
    const int i = blockIdx.x * 1024 + tid;
    sh[tid] = (i < n) ? data[i] : 0;
    __syncthreads();
    #pragma unroll
    for (int off = 1; off < 1024; off <<= 1) {
        int t = (tid >= off) ? sh[tid - off] : 0;
        __syncthreads();
        sh[tid] += t;
        __syncthreads();
    }
    if (i < n) data[i] = sh[tid];
    if (tid == 1023) blksum[blockIdx.x] = sh[1023];
}

__global__ __launch_bounds__(128) void scan2_kernel(int* __restrict__ blksum, int nb)
{
    __shared__ int sh[128];
    const int tid = threadIdx.x;
    int v = (tid < nb) ? blksum[tid] : 0;
    sh[tid] = v;
    __syncthreads();
    #pragma unroll
    for (int off = 1; off < 128; off <<= 1) {
        int t = (tid >= off) ? sh[tid - off] : 0;
        __syncthreads();
        sh[tid] += t;
        __syncthreads();
    }
    if (tid < nb) blksum[tid] = sh[tid] - v;   // exclusive
}

__global__ __launch_bounds__(1024) void scan3_kernel(
    int* __restrict__ data, int n, const int* __restrict__ blksum,
    int* __restrict__ cur, int nnodes)
{
    const int i = blockIdx.x * 1024 + threadIdx.x;
    if (i >= n) return;
    int v = data[i] + blksum[blockIdx.x];
    data[i] = v;
    if (i < nnodes) cur[i] = v;
}

__global__ __launch_bounds__(256) void fill_kernel(
    const int* __restrict__ src, const int* __restrict__ tgt,
    const float* __restrict__ w, int* __restrict__ cur,
    int2* __restrict__ edges, int E)
{
    int e = blockIdx.x * 256 + threadIdx.x;
    if (e >= E) return;
    int t = tgt[e];
    int pos = atomicAdd(&cur[t], 1);
    edges[pos] = make_int2(src[e], __float_as_int(w[e]));
}

// ---------------------------------------------------------------------------
// GEMM: C[M,OUTC] = A[M,K] @ W[K,OUTC].  128x64 tile, 256 thr, 8x4 reg block.
// A tile stored k-major in smem so each thread reads rows via 2x LDS.128.
// ---------------------------------------------------------------------------
template <int K, int OUTC>
__global__ __launch_bounds__(256) void gemm_kernel(
    const float* __restrict__ A, const float* __restrict__ W,
    float* __restrict__ C, int M)
{
    __shared__ float a_s[16][132];   // [k][row] (128 rows + pad)
    __shared__ float b_s[16][64];    // [k][col]

    const int tid = threadIdx.x;
    const int tx = tid & 15;        // 4 cols each
    const int ty = tid >> 4;        // 8 rows each
    const int row0 = blockIdx.x * 128;

    const int lk = tid & 15;        // A-load: k
    const int lr = tid >> 4;        // A-load: row base (16 rows / pass)
    const int bc = tid & 63;        // B-load: col
    const int bk = tid >> 6;        // B-load: k base

    float acc[8][4] = {};

    for (int k0 = 0; k0 < K; k0 += 16) {
        #pragma unroll
        for (int p = 0; p < 8; p++) {
            const int row = lr + p * 16;
            const int grow = row0 + row;
            float v = 0.f;
            if (grow < M) v = A[(size_t)grow * K + k0 + lk];
            a_s[lk][row] = v;
        }
        #pragma unroll
        for (int p = 0; p < 4; p++) {
            const int kk = bk + p * 4;
            float v = 0.f;
            if (OUTC == 64 || bc < OUTC) v = W[(k0 + kk) * OUTC + bc];
            b_s[kk][bc] = v;
        }
        __syncthreads();

        #pragma unroll
        for (int kk = 0; kk < 16; kk++) {
            const float4 a0 = *(const float4*)&a_s[kk][ty * 8];
            const float4 a1 = *(const float4*)&a_s[kk][ty * 8 + 4];
            const float4 b  = *(const float4*)&b_s[kk][tx * 4];
            const float av[8] = {a0.x, a0.y, a0.z, a0.w, a1.x, a1.y, a1.z, a1.w};
            #pragma unroll
            for (int i = 0; i < 8; i++) {
                acc[i][0] += av[i] * b.x;
                acc[i][1] += av[i] * b.y;
                acc[i][2] += av[i] * b.z;
                acc[i][3] += av[i] * b.w;
            }
        }
        __syncthreads();
    }

    if (OUTC == 64 || tx * 4 < OUTC) {
        #pragma unroll
        for (int i = 0; i < 8; i++) {
            const int row = row0 + ty * 8 + i;
            if (row < M) {
                *(float4*)&C[(size_t)row * OUTC + tx * 4] =
                    make_float4(acc[i][0], acc[i][1], acc[i][2], acc[i][3]);
            }
        }
    }
}

// ---------------------------------------------------------------------------
// CSR aggregate + fused epilogue.  16 threads per node, one float4 each.
// MODE 0: h = relu(agg+b)          (layer 0)
// MODE 1: h = relu(agg+b) + h      (residual layers)
// MODE 2: out = log_softmax(agg+b) (final layer, COLS=40)
// ---------------------------------------------------------------------------
template <int COLS, int MODE>
__global__ __launch_bounds__(256) void csr_agg_kernel(
    const float* __restrict__ sup, const int* __restrict__ row_off,
    const int2* __restrict__ edges, const float* __restrict__ bias,
    float* __restrict__ h, float* __restrict__ out, int M)
{
    constexpr int F4 = COLS / 4;
    const int gid = blockIdx.x * 256 + threadIdx.x;
    const int node = gid >> 4;
    const int lane = gid & 15;
    if (node >= M) return;

    const bool active = (lane < F4);
    float4 acc = make_float4(0.f, 0.f, 0.f, 0.f);

    if (active) {
        const int beg = row_off[node];
        const int end = row_off[node + 1];
        int j = beg;
        for (; j + 1 < end; j += 2) {
            const int2 e0 = edges[j];
            const int2 e1 = edges[j + 1];
            const float4 v0 = ((const float4*)(sup + (size_t)e0.x * COLS))[lane];
            const float4 v1 = ((const float4*)(sup + (size_t)e1.x * COLS))[lane];
            const float w0 = __int_as_float(e0.y);
            const float w1 = __int_as_float(e1.y);
            acc.x += v0.x * w0; acc.y += v0.y * w0;
            acc.z += v0.z * w0; acc.w += v0.w * w0;
            acc.x += v1.x * w1; acc.y += v1.y * w1;
            acc.z += v1.z * w1; acc.w += v1.w * w1;
        }
        if (j < end) {
            const int2 e0 = edges[j];
            const float4 v0 = ((const float4*)(sup + (size_t)e0.x * COLS))[lane];
            const float w0 = __int_as_float(e0.y);
            acc.x += v0.x * w0; acc.y += v0.y * w0;
            acc.z += v0.z * w0; acc.w += v0.w * w0;
        }
    }

    if (MODE == 0 || MODE == 1) {
        const float4 b = ((const float4*)bias)[lane];
        acc.x = fmaxf(acc.x + b.x, 0.f);
        acc.y = fmaxf(acc.y + b.y, 0.f);
        acc.z = fmaxf(acc.z + b.z, 0.f);
        acc.w = fmaxf(acc.w + b.w, 0.f);
        if (MODE == 1) {
            const float4 r = ((const float4*)(h + (size_t)node * COLS))[lane];
            acc.x += r.x; acc.y += r.y; acc.z += r.z; acc.w += r.w;
        }
        ((float4*)(h + (size_t)node * COLS))[lane] = acc;
    } else {
        float m = -INFINITY;
        if (active) {
            const float4 b = ((const float4*)(bias))[lane];
            acc.x += b.x; acc.y += b.y; acc.z += b.z; acc.w += b.w;
            m = fmaxf(fmaxf(acc.x, acc.y), fmaxf(acc.z, acc.w));
        }
        #pragma unroll
        for (int off = 8; off > 0; off >>= 1)
            m = fmaxf(m, __shfl_xor_sync(0xFFFFFFFFu, m, off));
        float s = 0.f;
        if (active)
            s = expf(acc.x - m) + expf(acc.y - m) + expf(acc.z - m) + expf(acc.w - m);
        #pragma unroll
        for (int off = 8; off > 0; off >>= 1)
            s += __shfl_xor_sync(0xFFFFFFFFu, s, off);
        const float lse = m + logf(s);
        if (active) {
            float* o = out + (size_t)node * COLS + lane * 4;
            o[0] = acc.x - lse; o[1] = acc.y - lse;
            o[2] = acc.z - lse; o[3] = acc.w - lse;
        }
    }
}

// ---------------------------------------------------------------------------
// Launch
// ---------------------------------------------------------------------------
extern "C" void kernel_launch(void* const* d_in, const int* in_sizes, int n_in,
                              void* d_out, int out_size)
{
    const float* x   = (const float*)d_in[0];
    const int*   src = (const int*)d_in[1];
    const int*   tgt = (const int*)d_in[2];
    const float* mw  = (const float*)d_in[3];
    const float* W0  = (const float*)d_in[4];
    const float* b0  = (const float*)d_in[5];
    const float* W1  = (const float*)d_in[6];
    const float* b1  = (const float*)d_in[7];
    const float* W2  = (const float*)d_in[8];
    const float* b2  = (const float*)d_in[9];
    const float* W3  = (const float*)d_in[10];
    const float* b3  = (const float*)d_in[11];
    float* out = (float*)d_out;

    const int M = NN;
    const int E = in_sizes[1];

    float *sup, *h;
    int *cnt, *cur, *blksum;
    int2 *edges;
    cudaGetSymbolAddress((void**)&sup, g_sup);
    cudaGetSymbolAddress((void**)&h, g_h);
    cudaGetSymbolAddress((void**)&cnt, g_cnt);
    cudaGetSymbolAddress((void**)&cur, g_cur);
    cudaGetSymbolAddress((void**)&blksum, g_blksum);
    cudaGetSymbolAddress((void**)&edges, g_edge);

    const int nscan = M + 1;
    const int scan_blocks = (nscan + 1023) / 1024;        // 98
    const int eblocks = (E + 255) / 256;                  // 6250
    const int gemm_blocks = (M + 127) / 128;              // 782
    const int agg_blocks = (M * 16 + 255) / 256;          // 6250

    // ---- CSR build (by target) ----
    cudaMemsetAsync(cnt, 0, (size_t)nscan * sizeof(int));
    hist_kernel<<<eblocks, 256>>>(tgt, cnt, E);
    scan1_kernel<<<scan_blocks, 1024>>>(cnt, nscan, blksum);
    scan2_kernel<<<1, 128>>>(blksum, scan_blocks);
    scan3_kernel<<<scan_blocks, 1024>>>(cnt, nscan, blksum, cur, M);
    fill_kernel<<<eblocks, 256>>>(src, tgt, mw, cur, edges, E);

    // ---- Layer 0: h = relu(agg(x@W0) + b0)
    gemm_kernel<128, 64><<<gemm_blocks, 256>>>(x, W0, sup, M);
    csr_agg_kernel<64, 0><<<agg_blocks, 256>>>(sup, cnt, edges, b0, h, out, M);

    // ---- Layer 1: h = relu(agg(h@W1) + b1) + h
    gemm_kernel<64, 64><<<gemm_blocks, 256>>>(h, W1, sup, M);
    csr_agg_kernel<64, 1><<<agg_blocks, 256>>>(sup, cnt, edges, b1, h, out, M);

    // ---- Layer 2: h = relu(agg(h@W2) + b2) + h
    gemm_kernel<64, 64><<<gemm_blocks, 256>>>(h, W2, sup, M);
    csr_agg_kernel<64, 1><<<agg_blocks, 256>>>(sup, cnt, edges, b2, h, out, M);

    // ---- Layer 3: out = log_softmax(agg(h@W3) + b3)
    gemm_kernel<64, 40><<<gemm_blocks, 256>>>(h, W3, sup, M);
    csr_agg_kernel<40, 2><<<agg_blocks, 256>>>(sup, cnt, edges, b3, h, out, M);
}

// round 3
// speedup vs baseline: 1.9279x; 1.1733x over previous
#include <cuda_runtime.h>
#include <cuda_fp16.h>
#include <math.h>

#define NN 100000
#define EE 1600000

// Scratch (device globals — no allocations allowed)
__device__ __align__(256) __half g_sup16[NN * 64];   // fp16 support (layers 0-2)
__device__ __align__(256) float  g_sup32[NN * 64];   // fp32 support (layer 3)
__device__ __align__(256) float  g_h[NN * 64];       // hidden state (fp32)
__device__ __align__(256) int    g_cnt[NN + 1];      // counts -> row offsets
__device__ __align__(256) int    g_cur[NN];          // fill cursors
__device__ __align__(256) int2   g_edge[EE];         // CSR payload: (src, w bits)
__device__ __align__(256) int    g_blksum[256];      // scan partials

// ---------------------------------------------------------------------------
// CSR build: histogram -> scan (3 pass) -> fill
// ---------------------------------------------------------------------------
__global__ __launch_bounds__(256) void hist_kernel(
    const int* __restrict__ tgt, int* __restrict__ cnt, int E)
{
    int e = blockIdx.x * 256 + threadIdx.x;
    if (e < E) atomicAdd(&cnt[tgt[e] + 1], 1);
}

__global__ __launch_bounds__(1024) void scan1_kernel(
    int* __restrict__ data, int n, int* __restrict__ blksum)
{
    __shared__ int wsum[32];
    const int tid = threadIdx.x;
    const int lane = tid & 31;
    const int warp = tid >> 5;
    const int i = blockIdx.x * 1024 + tid;
    int v = (i < n) ? data[i] : 0;
    #pragma unroll
    for (int off = 1; off < 32; off <<= 1) {
        int t = __shfl_up_sync(0xFFFFFFFFu, v, off);
        if (lane >= off) v += t;
    }
    if (lane == 31) wsum[warp] = v;
    __syncthreads();
    if (warp == 0) {
        int s = wsum[lane];
        #pragma unroll
        for (int off = 1; off < 32; off <<= 1) {
            int t = __shfl_up_sync(0xFFFFFFFFu, s, off);
            if (lane >= off) s += t;
        }
        wsum[lane] = s;
    }
    __syncthreads();
    if (warp > 0) v += wsum[warp - 1];
    if (i < n) data[i] = v;
    if (tid == 1023) blksum[blockIdx.x] = v;
}

__global__ __launch_bounds__(128) void scan2_kernel(int* __restrict__ blksum, int nb)
{
    __shared__ int sh[128];
    const int tid = threadIdx.x;
    int v = (tid < nb) ? blksum[tid] : 0;
    sh[tid] = v;
    __syncthreads();
    #pragma unroll
    for (int off = 1; off < 128; off <<= 1) {
        int t = (tid >= off) ? sh[tid - off] : 0;
        __syncthreads();
        sh[tid] += t;
        __syncthreads();
    }
    if (tid < nb) blksum[tid] = sh[tid] - v;   // exclusive
}

__global__ __launch_bounds__(1024) void scan3_kernel(
    int* __restrict__ data, int n, const int* __restrict__ blksum,
    int* __restrict__ cur, int nnodes)
{
    const int i = blockIdx.x * 1024 + threadIdx.x;
    if (i >= n) return;
    int v = data[i] + blksum[blockIdx.x];
    data[i] = v;
    if (i < nnodes) cur[i] = v;
}

__global__ __launch_bounds__(256) void fill_kernel(
    const int* __restrict__ src, const int* __restrict__ tgt,
    const float* __restrict__ w, int* __restrict__ cur,
    int2* __restrict__ edges, int E)
{
    int e = blockIdx.x * 256 + threadIdx.x;
    if (e >= E) return;
    int t = tgt[e];
    int pos = atomicAdd(&cur[t], 1);
    edges[pos] = make_int2(src[e], __float_as_int(w[e]));
}

// ---------------------------------------------------------------------------
// GEMM: C[M,OUTC] = A[M,K] @ W[K,OUTC].  128x64 tile, 256 thr, 8x4 reg block.
// HALF_OUT: store fp16 (for layers whose agg gathers fp16).
// ---------------------------------------------------------------------------
template <int K, int OUTC, bool HALF_OUT>
__global__ __launch_bounds__(256) void gemm_kernel(
    const float* __restrict__ A, const float* __restrict__ W,
    float* __restrict__ C32, __half* __restrict__ C16, int M)
{
    __shared__ float a_s[16][132];   // [k][row] (128 rows + pad)
    __shared__ float b_s[16][64];    // [k][col]

    const int tid = threadIdx.x;
    const int tx = tid & 15;        // 4 cols each
    const int ty = tid >> 4;        // 8 rows each
    const int row0 = blockIdx.x * 128;

    const int lk = tid & 15;        // A-load: k
    const int lr = tid >> 4;        // A-load: row base
    const int bc = tid & 63;        // B-load: col
    const int bk = tid >> 6;        // B-load: k base

    float acc[8][4] = {};

    for (int k0 = 0; k0 < K; k0 += 16) {
        #pragma unroll
        for (int p = 0; p < 8; p++) {
            const int row = lr + p * 16;
            const int grow = row0 + row;
            float v = 0.f;
            if (grow < M) v = A[(size_t)grow * K + k0 + lk];
            a_s[lk][row] = v;
        }
        #pragma unroll
        for (int p = 0; p < 4; p++) {
            const int kk = bk + p * 4;
            float v = 0.f;
            if (OUTC == 64 || bc < OUTC) v = W[(k0 + kk) * OUTC + bc];
            b_s[kk][bc] = v;
        }
        __syncthreads();

        #pragma unroll
        for (int kk = 0; kk < 16; kk++) {
            const float4 a0 = *(const float4*)&a_s[kk][ty * 8];
            const float4 a1 = *(const float4*)&a_s[kk][ty * 8 + 4];
            const float4 b  = *(const float4*)&b_s[kk][tx * 4];
            const float av[8] = {a0.x, a0.y, a0.z, a0.w, a1.x, a1.y, a1.z, a1.w};
            #pragma unroll
            for (int i = 0; i < 8; i++) {
                acc[i][0] += av[i] * b.x;
                acc[i][1] += av[i] * b.y;
                acc[i][2] += av[i] * b.z;
                acc[i][3] += av[i] * b.w;
            }
        }
        __syncthreads();
    }

    if (OUTC == 64 || tx * 4 < OUTC) {
        #pragma unroll
        for (int i = 0; i < 8; i++) {
            const int row = row0 + ty * 8 + i;
            if (row < M) {
                if (HALF_OUT) {
                    uint2 st;
                    __half2 p0 = __floats2half2_rn(acc[i][0], acc[i][1]);
                    __half2 p1 = __floats2half2_rn(acc[i][2], acc[i][3]);
                    st.x = *(const unsigned*)&p0;
                    st.y = *(const unsigned*)&p1;
                    *(uint2*)&C16[(size_t)row * OUTC + tx * 4] = st;
                } else {
                    *(float4*)&C32[(size_t)row * OUTC + tx * 4] =
                        make_float4(acc[i][0], acc[i][1], acc[i][2], acc[i][3]);
                }
            }
        }
    }
}

// ---------------------------------------------------------------------------
// fp16 CSR aggregate (COLS=64) + fused epilogue. 8 threads/node, 8 halves each.
// MODE 0: h = relu(agg+b);  MODE 1: h = relu(agg+b) + h
// ---------------------------------------------------------------------------
__device__ __forceinline__ void acc_edge16(
    float acc[8], const __half* __restrict__ sup, int s, float w, int lane)
{
    const uint4 raw = *(const uint4*)(sup + (size_t)s * 64 + lane * 8);
    const __half2* hp = (const __half2*)&raw;
    #pragma unroll
    for (int p = 0; p < 4; p++) {
        const float2 f = __half22float2(hp[p]);
        acc[p * 2 + 0] += f.x * w;
        acc[p * 2 + 1] += f.y * w;
    }
}

template <int MODE>
__global__ __launch_bounds__(256) void csr_agg16_kernel(
    const __half* __restrict__ sup, const int* __restrict__ row_off,
    const int2* __restrict__ edges, const float* __restrict__ bias,
    float* __restrict__ h, int M)
{
    const int gid = blockIdx.x * 256 + threadIdx.x;
    const int node = gid >> 3;
    const int lane = gid & 7;
    if (node >= M) return;

    const int beg = row_off[node];
    const int end = row_off[node + 1];

    float acc[8] = {};
    int j = beg;
    for (; j + 1 < end; j += 2) {
        const int2 e0 = edges[j];
        const int2 e1 = edges[j + 1];
        acc_edge16(acc, sup, e0.x, __int_as_float(e0.y), lane);
        acc_edge16(acc, sup, e1.x, __int_as_float(e1.y), lane);
    }
    if (j < end) {
        const int2 e0 = edges[j];
        acc_edge16(acc, sup, e0.x, __int_as_float(e0.y), lane);
    }

    float* hp = h + (size_t)node * 64 + lane * 8;
    const float4 b0 = ((const float4*)bias)[lane * 2];
    const float4 b1 = ((const float4*)bias)[lane * 2 + 1];
    const float bb[8] = {b0.x, b0.y, b0.z, b0.w, b1.x, b1.y, b1.z, b1.w};
    float4 o0, o1;
    float* ov = (float*)&o0;   // o0,o1 contiguous? not guaranteed; handle separately
    float res[8];
    #pragma unroll
    for (int p = 0; p < 8; p++) res[p] = fmaxf(acc[p] + bb[p], 0.f);
    if (MODE == 1) {
        const float4 r0 = *(const float4*)(hp);
        const float4 r1 = *(const float4*)(hp + 4);
        res[0] += r0.x; res[1] += r0.y; res[2] += r0.z; res[3] += r0.w;
        res[4] += r1.x; res[5] += r1.y; res[6] += r1.z; res[7] += r1.w;
    }
    o0 = make_float4(res[0], res[1], res[2], res[3]);
    o1 = make_float4(res[4], res[5], res[6], res[7]);
    (void)ov;
    *(float4*)(hp) = o0;
    *(float4*)(hp + 4) = o1;
}

// ---------------------------------------------------------------------------
// fp32 CSR aggregate, COLS=40, fused log_softmax (final layer).
// 16 threads/node, float4 each (lanes 0-9 active).
// ---------------------------------------------------------------------------
__global__ __launch_bounds__(256) void csr_agg40_final_kernel(
    const float* __restrict__ sup, const int* __restrict__ row_off,
    const int2* __restrict__ edges, const float* __restrict__ bias,
    float* __restrict__ out, int M)
{
    constexpr int COLS = 40;
    constexpr int F4 = 10;
    const int gid = blockIdx.x * 256 + threadIdx.x;
    const int node = gid >> 4;
    const int lane = gid & 15;
    if (node >= M) return;

    const bool active = (lane < F4);
    float4 acc = make_float4(0.f, 0.f, 0.f, 0.f);

    if (active) {
        const int beg = row_off[node];
        const int end = row_off[node + 1];
        int j = beg;
        for (; j + 1 < end; j += 2) {
            const int2 e0 = edges[j];
            const int2 e1 = edges[j + 1];
            const float4 v0 = ((const float4*)(sup + (size_t)e0.x * COLS))[lane];
            const float4 v1 = ((const float4*)(sup + (size_t)e1.x * COLS))[lane];
            const float w0 = __int_as_float(e0.y);
            const float w1 = __int_as_float(e1.y);
            acc.x += v0.x * w0; acc.y += v0.y * w0;
            acc.z += v0.z * w0; acc.w += v0.w * w0;
            acc.x += v1.x * w1; acc.y += v1.y * w1;
            acc.z += v1.z * w1; acc.w += v1.w * w1;
        }
        if (j < end) {
            const int2 e0 = edges[j];
            const float4 v0 = ((const float4*)(sup + (size_t)e0.x * COLS))[lane];
            const float w0 = __int_as_float(e0.y);
            acc.x += v0.x * w0; acc.y += v0.y * w0;
            acc.z += v0.z * w0; acc.w += v0.w * w0;
        }
    }

    float m = -INFINITY;
    if (active) {
        const float4 b = ((const float4*)bias)[lane];
        acc.x += b.x; acc.y += b.y; acc.z += b.z; acc.w += b.w;
        m = fmaxf(fmaxf(acc.x, acc.y), fmaxf(acc.z, acc.w));
    }
    #pragma unroll
    for (int off = 8; off > 0; off >>= 1)
        m = fmaxf(m, __shfl_xor_sync(0xFFFFFFFFu, m, off));
    float s = 0.f;
    if (active)
        s = expf(acc.x - m) + expf(acc.y - m) + expf(acc.z - m) + expf(acc.w - m);
    #pragma unroll
    for (int off = 8; off > 0; off >>= 1)
        s += __shfl_xor_sync(0xFFFFFFFFu, s, off);
    const float lse = m + logf(s);
    if (active) {
        float* o = out + (size_t)node * COLS + lane * 4;
        o[0] = acc.x - lse; o[1] = acc.y - lse;
        o[2] = acc.z - lse; o[3] = acc.w - lse;
    }
}

// ---------------------------------------------------------------------------
// Launch
// ---------------------------------------------------------------------------
extern "C" void kernel_launch(void* const* d_in, const int* in_sizes, int n_in,
                              void* d_out, int out_size)
{
    const float* x   = (const float*)d_in[0];
    const int*   src = (const int*)d_in[1];
    const int*   tgt = (const int*)d_in[2];
    const float* mw  = (const float*)d_in[3];
    const float* W0  = (const float*)d_in[4];
    const float* b0  = (const float*)d_in[5];
    const float* W1  = (const float*)d_in[6];
    const float* b1  = (const float*)d_in[7];
    const float* W2  = (const float*)d_in[8];
    const float* b2  = (const float*)d_in[9];
    const float* W3  = (const float*)d_in[10];
    const float* b3  = (const float*)d_in[11];
    float* out = (float*)d_out;

    const int M = NN;
    const int E = in_sizes[1];

    float *sup32, *h;
    __half *sup16;
    int *cnt, *cur, *blksum;
    int2 *edges;
    cudaGetSymbolAddress((void**)&sup32, g_sup32);
    cudaGetSymbolAddress((void**)&sup16, g_sup16);
    cudaGetSymbolAddress((void**)&h, g_h);
    cudaGetSymbolAddress((void**)&cnt, g_cnt);
    cudaGetSymbolAddress((void**)&cur, g_cur);
    cudaGetSymbolAddress((void**)&blksum, g_blksum);
    cudaGetSymbolAddress((void**)&edges, g_edge);

    const int nscan = M + 1;
    const int scan_blocks = (nscan + 1023) / 1024;
    const int eblocks = (E + 255) / 256;
    const int gemm_blocks = (M + 127) / 128;
    const int agg16_blocks = (M * 8 + 255) / 256;
    const int agg40_blocks = (M * 16 + 255) / 256;

    // ---- CSR build (by target) ----
    cudaMemsetAsync(cnt, 0, (size_t)nscan * sizeof(int));
    hist_kernel<<<eblocks, 256>>>(tgt, cnt, E);
    scan1_kernel<<<scan_blocks, 1024>>>(cnt, nscan, blksum);
    scan2_kernel<<<1, 128>>>(blksum, scan_blocks);
    scan3_kernel<<<scan_blocks, 1024>>>(cnt, nscan, blksum, cur, M);
    fill_kernel<<<eblocks, 256>>>(src, tgt, mw, cur, edges, E);

    // ---- Layer 0: h = relu(agg(x@W0) + b0)
    gemm_kernel<128, 64, true><<<gemm_blocks, 256>>>(x, W0, nullptr, sup16, M);
    csr_agg16_kernel<0><<<agg16_blocks, 256>>>(sup16, cnt, edges, b0, h, M);

    // ---- Layer 1: h = relu(agg(h@W1) + b1) + h
    gemm_kernel<64, 64, true><<<gemm_blocks, 256>>>(h, W1, nullptr, sup16, M);
    csr_agg16_kernel<1><<<agg16_blocks, 256>>>(sup16, cnt, edges, b1, h, M);

    // ---- Layer 2: h = relu(agg(h@W2) + b2) + h
    gemm_kernel<64, 64, true><<<gemm_blocks, 256>>>(h, W2, nullptr, sup16, M);
    csr_agg16_kernel<1><<<agg16_blocks, 256>>>(sup16, cnt, edges, b2, h, M);

    // ---- Layer 3: out = log_softmax(agg(h@W3) + b3)
    gemm_kernel<64, 40, false><<<gemm_blocks, 256>>>(h, W3, sup32, nullptr, M);
    csr_agg40_final_kernel<<<agg40_blocks, 256>>>(sup32, cnt, edges, b3, out, M);
}

// round 5
// speedup vs baseline: 2.7463x; 1.4245x over previous
#include <cuda_runtime.h>
#include <cuda_fp16.h>
#include <cstdint>
#include <math.h>

#define NN 100000
#define EE 1600000

// Scratch (device globals — no allocations allowed)
__device__ __align__(256) __half g_sup16[NN * 64];   // fp16 support (all layers)
__device__ __align__(256) float  g_h[NN * 64];       // hidden state (fp32)
__device__ __align__(256) __half g_h16[NN * 64];     // fp16 copy of h (GEMM A input)
__device__ __align__(256) int    g_cnt[NN + 1];      // counts -> row offsets
__device__ __align__(256) int    g_cur[NN];          // fill cursors
__device__ __align__(256) int2   g_edge[EE];         // CSR payload: (src, w bits)
__device__ __align__(256) int    g_blksum[256];      // scan partials

// ---------------------------------------------------------------------------
// CSR build: histogram -> scan (3 pass) -> fill
// ---------------------------------------------------------------------------
__global__ __launch_bounds__(256) void hist_kernel(
    const int* __restrict__ tgt, int* __restrict__ cnt, int E)
{
    int e = blockIdx.x * 256 + threadIdx.x;
    if (e < E) atomicAdd(&cnt[tgt[e] + 1], 1);
}

__global__ __launch_bounds__(1024) void scan1_kernel(
    int* __restrict__ data, int n, int* __restrict__ blksum)
{
    __shared__ int wsum[32];
    const int tid = threadIdx.x;
    const int lane = tid & 31;
    const int warp = tid >> 5;
    const int i = blockIdx.x * 1024 + tid;
    int v = (i < n) ? data[i] : 0;
    #pragma unroll
    for (int off = 1; off < 32; off <<= 1) {
        int t = __shfl_up_sync(0xFFFFFFFFu, v, off);
        if (lane >= off) v += t;
    }
    if (lane == 31) wsum[warp] = v;
    __syncthreads();
    if (warp == 0) {
        int s = wsum[lane];
        #pragma unroll
        for (int off = 1; off < 32; off <<= 1) {
            int t = __shfl_up_sync(0xFFFFFFFFu, s, off);
            if (lane >= off) s += t;
        }
        wsum[lane] = s;
    }
    __syncthreads();
    if (warp > 0) v += wsum[warp - 1];
    if (i < n) data[i] = v;
    if (tid == 1023) blksum[blockIdx.x] = v;
}

__global__ __launch_bounds__(128) void scan2_kernel(int* __restrict__ blksum, int nb)
{
    __shared__ int sh[128];
    const int tid = threadIdx.x;
    int v = (tid < nb) ? blksum[tid] : 0;
    sh[tid] = v;
    __syncthreads();
    #pragma unroll
    for (int off = 1; off < 128; off <<= 1) {
        int t = (tid >= off) ? sh[tid - off] : 0;
        __syncthreads();
        sh[tid] += t;
        __syncthreads();
    }
    if (tid < nb) blksum[tid] = sh[tid] - v;   // exclusive
}

__global__ __launch_bounds__(1024) void scan3_kernel(
    int* __restrict__ data, int n, const int* __restrict__ blksum,
    int* __restrict__ cur, int nnodes)
{
    const int i = blockIdx.x * 1024 + threadIdx.x;
    if (i >= n) return;
    int v = data[i] + blksum[blockIdx.x];
    data[i] = v;
    if (i < nnodes) cur[i] = v;
}

__global__ __launch_bounds__(256) void fill_kernel(
    const int* __restrict__ src, const int* __restrict__ tgt,
    const float* __restrict__ w, int* __restrict__ cur,
    int2* __restrict__ edges, int E)
{
    int e = blockIdx.x * 256 + threadIdx.x;
    if (e >= E) return;
    int t = tgt[e];
    int pos = atomicAdd(&cur[t], 1);
    edges[pos] = make_int2(src[e], __float_as_int(w[e]));
}

// ---------------------------------------------------------------------------
// HMMA GEMM: C16[M,OUTC] = A[M,K] @ W[K,OUTC]  (fp16 in, fp32 accum, fp16 out)
// Tile: BM=128, BN=64, BK=64. 256 threads = 8 warps (4m x 2n), warp = 32x32.
// A_FP32: A is fp32 in global (layer 0's x), converted during smem load.
// ---------------------------------------------------------------------------
#define SMEM_STRIDE 72   // halves per row (144 B) -> conflict-free LDSM

__device__ __forceinline__ unsigned smem_u32(const void* p) {
    return (unsigned)__cvta_generic_to_shared(p);
}

__device__ __forceinline__ void ldsm_x4(unsigned& r0, unsigned& r1,
                                        unsigned& r2, unsigned& r3, unsigned a) {
    asm volatile("ldmatrix.sync.aligned.m8n8.x4.shared.b16 {%0,%1,%2,%3}, [%4];"
                 : "=r"(r0), "=r"(r1), "=r"(r2), "=r"(r3) : "r"(a));
}
__device__ __forceinline__ void ldsm_x4_t(unsigned& r0, unsigned& r1,
                                          unsigned& r2, unsigned& r3, unsigned a) {
    asm volatile("ldmatrix.sync.aligned.m8n8.x4.trans.shared.b16 {%0,%1,%2,%3}, [%4];"
                 : "=r"(r0), "=r"(r1), "=r"(r2), "=r"(r3) : "r"(a));
}
__device__ __forceinline__ void mma16816(float c[4], const unsigned a[4],
                                         unsigned b0, unsigned b1) {
    asm volatile(
        "mma.sync.aligned.m16n8k16.row.col.f32.f16.f16.f32 "
        "{%0,%1,%2,%3}, {%4,%5,%6,%7}, {%8,%9}, {%0,%1,%2,%3};"
        : "+f"(c[0]), "+f"(c[1]), "+f"(c[2]), "+f"(c[3])
        : "r"(a[0]), "r"(a[1]), "r"(a[2]), "r"(a[3]), "r"(b0), "r"(b1));
}

template <int K, int OUTC, bool A_FP32>
__global__ __launch_bounds__(256) void hgemm_kernel(
    const float* __restrict__ A32, const __half* __restrict__ A16,
    const float* __restrict__ W, __half* __restrict__ C16, int M)
{
    __shared__ __half a_s[128 * SMEM_STRIDE];
    __shared__ __half b_s[64 * SMEM_STRIDE];

    const int tid = threadIdx.x;
    const int lane = tid & 31;
    const int wid = tid >> 5;
    const int wm = (wid >> 1) * 32;   // warp m offset in tile
    const int wn = (wid & 1) * 32;    // warp n offset in tile
    const int row0 = blockIdx.x * 128;

    float c[2][4][4] = {};

    for (int k0 = 0; k0 < K; k0 += 64) {
        // ---- Load A tile: 128 rows x 64 halves ----
        if (A_FP32) {
            #pragma unroll
            for (int p = 0; p < 8; p++) {
                const int idx = tid + p * 256;
                const int row = idx >> 4;
                const int ch = idx & 15;
                const int grow = row0 + row;
                uint2 st = make_uint2(0u, 0u);
                if (grow < M) {
                    const float4 v = *(const float4*)&A32[(size_t)grow * K + k0 + ch * 4];
                    __half2 h0 = __floats2half2_rn(v.x, v.y);
                    __half2 h1 = __floats2half2_rn(v.z, v.w);
                    st.x = *(const unsigned*)&h0;
                    st.y = *(const unsigned*)&h1;
                }
                *(uint2*)&a_s[row * SMEM_STRIDE + ch * 4] = st;
            }
        } else {
            #pragma unroll
            for (int p = 0; p < 4; p++) {
                const int idx = tid + p * 256;
                const int row = idx >> 3;
                const int ch = idx & 7;
                const int grow = row0 + row;
                uint4 v = make_uint4(0u, 0u, 0u, 0u);
                if (grow < M) v = *(const uint4*)&A16[(size_t)grow * K + k0 + ch * 8];
                *(uint4*)&a_s[row * SMEM_STRIDE + ch * 8] = v;
            }
        }
        // ---- Load B tile: 64 rows x 64 cols (fp32 -> fp16, zero-pad) ----
        #pragma unroll
        for (int p = 0; p < 4; p++) {
            const int idx = tid + p * 256;
            const int row = idx >> 4;     // k within tile
            const int ch = idx & 15;      // 4-col chunk
            uint2 st = make_uint2(0u, 0u);
            if (OUTC == 64 || ch * 4 < OUTC) {
                const float4 v = *(const float4*)&W[(size_t)(k0 + row) * OUTC + ch * 4];
                __half2 h0 = __floats2half2_rn(v.x, v.y);
                __half2 h1 = __floats2half2_rn(v.z, v.w);
                st.x = *(const unsigned*)&h0;
                st.y = *(const unsigned*)&h1;
            }
            *(uint2*)&b_s[row * SMEM_STRIDE + ch * 4] = st;
        }
        __syncthreads();

        // ---- 4 k16 steps ----
        #pragma unroll
        for (int ks = 0; ks < 4; ks++) {
            const int k = ks * 16;
            unsigned a[2][4];
            #pragma unroll
            for (int mt = 0; mt < 2; mt++) {
                const int r = wm + mt * 16 + (lane & 15);
                const int cc = k + (lane >> 4) * 8;
                ldsm_x4(a[mt][0], a[mt][1], a[mt][2], a[mt][3],
                        smem_u32(&a_s[r * SMEM_STRIDE + cc]));
            }
            unsigned b[2][4];
            #pragma unroll
            for (int nt2 = 0; nt2 < 2; nt2++) {
                const int kr = k + (lane & 15);
                const int nc = wn + nt2 * 16 + (lane >> 4) * 8;
                ldsm_x4_t(b[nt2][0], b[nt2][1], b[nt2][2], b[nt2][3],
                          smem_u32(&b_s[kr * SMEM_STRIDE + nc]));
            }
            #pragma unroll
            for (int mt = 0; mt < 2; mt++)
                #pragma unroll
                for (int nt = 0; nt < 4; nt++)
                    mma16816(c[mt][nt], a[mt],
                             b[nt >> 1][(nt & 1) * 2], b[nt >> 1][(nt & 1) * 2 + 1]);
        }
        if (K > 64) __syncthreads();
    }

    // ---- Store C as fp16 ----
    #pragma unroll
    for (int mt = 0; mt < 2; mt++) {
        #pragma unroll
        for (int nt = 0; nt < 4; nt++) {
            const int col = wn + nt * 8 + (lane & 3) * 2;
            if (OUTC == 64 || col < OUTC) {
                const int r0 = row0 + wm + mt * 16 + (lane >> 2);
                if (r0 < M) {
                    __half2 v = __floats2half2_rn(c[mt][nt][0], c[mt][nt][1]);
                    *(__half2*)&C16[(size_t)r0 * OUTC + col] = v;
                }
                const int r1 = r0 + 8;
                if (r1 < M) {
                    __half2 v = __floats2half2_rn(c[mt][nt][2], c[mt][nt][3]);
                    *(__half2*)&C16[(size_t)r1 * OUTC + col] = v;
                }
            }
        }
    }
}

// ---------------------------------------------------------------------------
// fp16 CSR aggregate (COLS=64) + fused epilogue. 8 threads/node, 8 halves each.
// MODE 0: h = relu(agg+b);  MODE 1: h = relu(agg+b) + h.  Writes h32 and h16.
// ---------------------------------------------------------------------------
__device__ __forceinline__ void acc_edge16(
    float acc[8], const __half* __restrict__ sup, int s, float w, int lane)
{
    const uint4 raw = *(const uint4*)(sup + (size_t)s * 64 + lane * 8);
    const __half2* hp = (const __half2*)&raw;
    #pragma unroll
    for (int p = 0; p < 4; p++) {
        const float2 f = __half22float2(hp[p]);
        acc[p * 2 + 0] += f.x * w;
        acc[p * 2 + 1] += f.y * w;
    }
}

template <int MODE>
__global__ __launch_bounds__(256) void csr_agg16_kernel(
    const __half* __restrict__ sup, const int* __restrict__ row_off,
    const int2* __restrict__ edges, const float* __restrict__ bias,
    float* __restrict__ h, __half* __restrict__ h16, int M)
{
    const int gid = blockIdx.x * 256 + threadIdx.x;
    const int node = gid >> 3;
    const int lane = gid & 7;
    if (node >= M) return;

    const int beg = row_off[node];
    const int end = row_off[node + 1];

    float acc[8] = {};
    int j = beg;
    for (; j + 1 < end; j += 2) {
        const int2 e0 = edges[j];
        const int2 e1 = edges[j + 1];
        acc_edge16(acc, sup, e0.x, __int_as_float(e0.y), lane);
        acc_edge16(acc, sup, e1.x, __int_as_float(e1.y), lane);
    }
    if (j < end) {
        const int2 e0 = edges[j];
        acc_edge16(acc, sup, e0.x, __int_as_float(e0.y), lane);
    }

    float* hp = h + (size_t)node * 64 + lane * 8;
    const float4 b0 = ((const float4*)bias)[lane * 2];
    const float4 b1 = ((const float4*)bias)[lane * 2 + 1];
    const float bb[8] = {b0.x, b0.y, b0.z, b0.w, b1.x, b1.y, b1.z, b1.w};
    float res[8];
    #pragma unroll
    for (int p = 0; p < 8; p++) res[p] = fmaxf(acc[p] + bb[p], 0.f);
    if (MODE == 1) {
        const float4 r0 = *(const float4*)(hp);
        const float4 r1 = *(const float4*)(hp + 4);
        res[0] += r0.x; res[1] += r0.y; res[2] += r0.z; res[3] += r0.w;
        res[4] += r1.x; res[5] += r1.y; res[6] += r1.z; res[7] += r1.w;
    }
    *(float4*)(hp)     = make_float4(res[0], res[1], res[2], res[3]);
    *(float4*)(hp + 4) = make_float4(res[4], res[5], res[6], res[7]);

    uint4 st;
    __half2 q0 = __floats2half2_rn(res[0], res[1]);
    __half2 q1 = __floats2half2_rn(res[2], res[3]);
    __half2 q2 = __floats2half2_rn(res[4], res[5]);
    __half2 q3 = __floats2half2_rn(res[6], res[7]);
    st.x = *(const unsigned*)&q0; st.y = *(const unsigned*)&q1;
    st.z = *(const unsigned*)&q2; st.w = *(const unsigned*)&q3;
    *(uint4*)&h16[(size_t)node * 64 + lane * 8] = st;
}

// ---------------------------------------------------------------------------
// fp16 CSR aggregate, COLS=40, fused log_softmax (final layer).
// 16 threads/node; lanes 0-9 hold 4 halves (uint2) each.
// ---------------------------------------------------------------------------
__global__ __launch_bounds__(256) void csr_agg40_final_kernel(
    const __half* __restrict__ sup, const int* __restrict__ row_off,
    const int2* __restrict__ edges, const float* __restrict__ bias,
    float* __restrict__ out, int M)
{
    const int gid = blockIdx.x * 256 + threadIdx.x;
    const int node = gid >> 4;
    const int lane = gid & 15;
    if (node >= M) return;

    const bool active = (lane < 10);
    float a0 = 0.f, a1 = 0.f, a2 = 0.f, a3 = 0.f;

    if (active) {
        const int beg = row_off[node];
        const int end = row_off[node + 1];
        for (int j = beg; j < end; j++) {
            const int2 e = edges[j];
            const float w = __int_as_float(e.y);
            const uint2 raw = *(const uint2*)(sup + (size_t)e.x * 40 + lane * 4);
            const __half2* hp = (const __half2*)&raw;
            const float2 f0 = __half22float2(hp[0]);
            const float2 f1 = __half22float2(hp[1]);
            a0 += f0.x * w; a1 += f0.y * w;
            a2 += f1.x * w; a3 += f1.y * w;
        }
    }

    float m = -INFINITY;
    if (active) {
        const float* b = bias + lane * 4;
        a0 += b[0]; a1 += b[1]; a2 += b[2]; a3 += b[3];
        m = fmaxf(fmaxf(a0, a1), fmaxf(a2, a3));
    }
    #pragma unroll
    for (int off = 8; off > 0; off >>= 1)
        m = fmaxf(m, __shfl_xor_sync(0xFFFFFFFFu, m, off));
    float s = 0.f;
    if (active)
        s = expf(a0 - m) + expf(a1 - m) + expf(a2 - m) + expf(a3 - m);
    #pragma unroll
    for (int off = 8; off > 0; off >>= 1)
        s += __shfl_xor_sync(0xFFFFFFFFu, s, off);
    const float lse = m + logf(s);
    if (active) {
        float* o = out + (size_t)node * 40 + lane * 4;
        o[0] = a0 - lse; o[1] = a1 - lse; o[2] = a2 - lse; o[3] = a3 - lse;
    }
}

// ---------------------------------------------------------------------------
// Launch
// ---------------------------------------------------------------------------
extern "C" void kernel_launch(void* const* d_in, const int* in_sizes, int n_in,
                              void* d_out, int out_size)
{
    const float* x   = (const float*)d_in[0];
    const int*   src = (const int*)d_in[1];
    const int*   tgt = (const int*)d_in[2];
    const float* mw  = (const float*)d_in[3];
    const float* W0  = (const float*)d_in[4];
    const float* b0  = (const float*)d_in[5];
    const float* W1  = (const float*)d_in[6];
    const float* b1  = (const float*)d_in[7];
    const float* W2  = (const float*)d_in[8];
    const float* b2  = (const float*)d_in[9];
    const float* W3  = (const float*)d_in[10];
    const float* b3  = (const float*)d_in[11];
    float* out = (float*)d_out;

    const int M = NN;
    const int E = in_sizes[1];

    float *h;
    __half *sup16, *h16;
    int *cnt, *cur, *blksum;
    int2 *edges;
    cudaGetSymbolAddress((void**)&sup16, g_sup16);
    cudaGetSymbolAddress((void**)&h, g_h);
    cudaGetSymbolAddress((void**)&h16, g_h16);
    cudaGetSymbolAddress((void**)&cnt, g_cnt);
    cudaGetSymbolAddress((void**)&cur, g_cur);
    cudaGetSymbolAddress((void**)&blksum, g_blksum);
    cudaGetSymbolAddress((void**)&edges, g_edge);

    const int nscan = M + 1;
    const int scan_blocks = (nscan + 1023) / 1024;
    const int eblocks = (E + 255) / 256;
    const int gemm_blocks = (M + 127) / 128;
    const int agg16_blocks = (M * 8 + 255) / 256;
    const int agg40_blocks = (M * 16 + 255) / 256;

    // ---- CSR build (by target) ----
    cudaMemsetAsync(cnt, 0, (size_t)nscan * sizeof(int));
    hist_kernel<<<eblocks, 256>>>(tgt, cnt, E);
    scan1_kernel<<<scan_blocks, 1024>>>(cnt, nscan, blksum);
    scan2_kernel<<<1, 128>>>(blksum, scan_blocks);
    scan3_kernel<<<scan_blocks, 1024>>>(cnt, nscan, blksum, cur, M);
    fill_kernel<<<eblocks, 256>>>(src, tgt, mw, cur, edges, E);

    // ---- Layer 0: h = relu(agg(x@W0) + b0)
    hgemm_kernel<128, 64, true><<<gemm_blocks, 256>>>(x, (const __half*)0, W0, sup16, M);
    csr_agg16_kernel<0><<<agg16_blocks, 256>>>(sup16, cnt, edges, b0, h, h16, M);

    // ---- Layer 1: h = relu(agg(h@W1) + b1) + h
    hgemm_kernel<64, 64, false><<<gemm_blocks, 256>>>((const float*)0, h16, W1, sup16, M);
    csr_agg16_kernel<1><<<agg16_blocks, 256>>>(sup16, cnt, edges, b1, h, h16, M);

    // ---- Layer 2: h = relu(agg(h@W2) + b2) + h
    hgemm_kernel<64, 64, false><<<gemm_blocks, 256>>>((const float*)0, h16, W2, sup16, M);
    csr_agg16_kernel<1><<<agg16_blocks, 256>>>(sup16, cnt, edges, b2, h, h16, M);

    // ---- Layer 3: out = log_softmax(agg(h@W3) + b3)
    hgemm_kernel<64, 40, false><<<gemm_blocks, 256>>>((const float*)0, h16, W3, sup16, M);
    csr_agg40_final_kernel<<<agg40_blocks, 256>>>(sup16, cnt, edges, b3, out, M);
}